// round 1
// baseline (speedup 1.0000x reference)
#include <cuda_runtime.h>

#define BATCH 2048
#define NF 32
#define DIM 64
#define NPAIR 496
#define TILE_B 64

// out[b, p, e] = (sum_d fe[b, i(p), d] * W[p, d, e]) * fe[b, j(p), e]
__global__ __launch_bounds__(256) void bilinear_kernel(
    const float* __restrict__ fe,   // [BATCH, NF, DIM]
    const float* __restrict__ Wg,   // [NPAIR, DIM, DIM]
    float* __restrict__ out)        // [BATCH, NPAIR, DIM]
{
    const int p     = blockIdx.y;       // pair index 0..495
    const int btile = blockIdx.x;       // 0..31 (64 batch rows each)
    const int tid   = threadIdx.x;

    // Decode (i, j) from triu_indices(NF, k=1) row-major order.
    int i = 0, rem = p;
    while (rem >= NF - 1 - i) { rem -= NF - 1 - i; ++i; }
    const int j = i + 1 + rem;

    __shared__ float As[DIM][TILE_B + 4];  // transposed: As[d][row], pad for alignment/banks
    __shared__ float Ws[DIM][DIM];         // Ws[d][e]

    // ---- Load A tile (64 rows x 64 d), stored transposed ----
    {
        const int r = tid >> 2;        // 0..63
        const int m = tid & 3;         // 0..3
        const float* src = fe + ((size_t)(btile * TILE_B + r) * NF + i) * DIM + 4 * m;
        #pragma unroll
        for (int q = 0; q < 4; ++q) {
            float4 v = *reinterpret_cast<const float4*>(src + 16 * q);
            const int d = 16 * q + 4 * m;
            As[d + 0][r] = v.x;
            As[d + 1][r] = v.y;
            As[d + 2][r] = v.z;
            As[d + 3][r] = v.w;
        }
    }
    // ---- Load W_p (64x64, contiguous) ----
    {
        const float4* src = reinterpret_cast<const float4*>(Wg + (size_t)p * DIM * DIM);
        float4* dst = reinterpret_cast<float4*>(&Ws[0][0]);
        #pragma unroll
        for (int q = 0; q < 4; ++q)
            dst[tid + 256 * q] = src[tid + 256 * q];
    }
    __syncthreads();

    // ---- Compute: each thread owns a 4x4 tile of the 64x64 output ----
    const int tr = (tid >> 4) * 4;   // row base
    const int tc = (tid & 15) * 4;   // col base

    float acc[4][4] = {};
    #pragma unroll 16
    for (int k = 0; k < DIM; ++k) {
        float4 a = *reinterpret_cast<const float4*>(&As[k][tr]);
        float4 w = *reinterpret_cast<const float4*>(&Ws[k][tc]);
        acc[0][0] += a.x * w.x; acc[0][1] += a.x * w.y; acc[0][2] += a.x * w.z; acc[0][3] += a.x * w.w;
        acc[1][0] += a.y * w.x; acc[1][1] += a.y * w.y; acc[1][2] += a.y * w.z; acc[1][3] += a.y * w.w;
        acc[2][0] += a.z * w.x; acc[2][1] += a.z * w.y; acc[2][2] += a.z * w.z; acc[2][3] += a.z * w.w;
        acc[3][0] += a.w * w.x; acc[3][1] += a.w * w.y; acc[3][2] += a.w * w.z; acc[3][3] += a.w * w.w;
    }

    // ---- Epilogue: scale by v_j and store ----
    const int b0 = btile * TILE_B + tr;
    #pragma unroll
    for (int rr = 0; rr < 4; ++rr) {
        const int b = b0 + rr;
        float4 vj = *reinterpret_cast<const float4*>(fe + ((size_t)b * NF + j) * DIM + tc);
        float4 o;
        o.x = acc[rr][0] * vj.x;
        o.y = acc[rr][1] * vj.y;
        o.z = acc[rr][2] * vj.z;
        o.w = acc[rr][3] * vj.w;
        *reinterpret_cast<float4*>(out + ((size_t)b * NPAIR + p) * DIM + tc) = o;
    }
}

extern "C" void kernel_launch(void* const* d_in, const int* in_sizes, int n_in,
                              void* d_out, int out_size) {
    const float* fe = (const float*)d_in[0];   // feature_emb [2048, 32, 64] fp32
    const float* W  = (const float*)d_in[1];   // bilinear_W [496, 64, 64] fp32
    float* out = (float*)d_out;                // [2048, 496, 64] fp32

    dim3 grid(BATCH / TILE_B, NPAIR);  // (32, 496)
    bilinear_kernel<<<grid, 256>>>(fe, W, out);
}